// round 1
// baseline (speedup 1.0000x reference)
#include <cuda_runtime.h>
#include <cstdint>

// Skeleton forward kinematics: 6d rotations -> world-space joint positions.
// angles: [B, 16, 6] f32   xyz: [1, 16, 3] f32   out: [B, 16, 3] f32
//
// Tree (PARENT -> CHILD): 0-1-2-3, then from 3: (4-5), (6-7-8-9-10), (11-...-15).
// One thread per batch element. HBM-bound (~144MB traffic -> ~19us floor).

namespace {

constexpr int NJ = 16;

__device__ __forceinline__ void rot6d(const float a0, const float a1, const float a2,
                                      const float a3, const float a4, const float a5,
                                      float R[9]) {
    // b1 = normalize(a[0:3])
    float n1 = rsqrtf(a0 * a0 + a1 * a1 + a2 * a2);
    float b1x = a0 * n1, b1y = a1 * n1, b1z = a2 * n1;
    // b2 = normalize(a[3:6] - dot(b1, a[3:6]) * b1)
    float d = b1x * a3 + b1y * a4 + b1z * a5;
    float b2x = a3 - d * b1x, b2y = a4 - d * b1y, b2z = a5 - d * b1z;
    float n2 = rsqrtf(b2x * b2x + b2y * b2y + b2z * b2z);
    b2x *= n2; b2y *= n2; b2z *= n2;
    // b3 = cross(b1, b2)
    float b3x = b1y * b2z - b1z * b2y;
    float b3y = b1z * b2x - b1x * b2z;
    float b3z = b1x * b2y - b1y * b2x;
    R[0] = b1x; R[1] = b1y; R[2] = b1z;
    R[3] = b2x; R[4] = b2y; R[5] = b2z;
    R[6] = b3x; R[7] = b3y; R[8] = b3z;
}

__global__ __launch_bounds__(256)
void skeleton_fk_kernel(const float* __restrict__ angles,
                        const float* __restrict__ xyz,
                        float* __restrict__ out,
                        int batch) {
    int b = blockIdx.x * blockDim.x + threadIdx.x;
    if (b >= batch) return;

    const float* __restrict__ ab = angles + (size_t)b * (NJ * 6);

    // Reference joint positions (warp-uniform loads; L1-resident after first warp).
    float ref[NJ * 3];
#pragma unroll
    for (int i = 0; i < NJ * 3; ++i) ref[i] = __ldg(xyz + i);

    // Per-joint 6d angle load: three float2 (8B-aligned: offset 6j is even).
    float a[NJ * 6];
#pragma unroll
    for (int j = 0; j < NJ * 3; ++j) {
        float2 v = __ldg(reinterpret_cast<const float2*>(ab) + j);
        a[2 * j + 0] = v.x;
        a[2 * j + 1] = v.y;
    }

    // World transforms. Fully-unrolled constant-index topology: ptxas
    // register-allocates and dead-codes unused Rw (5, 10, 15 never parents).
    float Rw[NJ * 9];
    float pw[NJ * 3];

    // Root joint 0: Rw[0] = R0, pw[0] = R0 @ ref[0]
    rot6d(a[0], a[1], a[2], a[3], a[4], a[5], &Rw[0]);
    {
        float tx = ref[0], ty = ref[1], tz = ref[2];
        pw[0] = Rw[0] * tx + Rw[1] * ty + Rw[2] * tz;
        pw[1] = Rw[3] * tx + Rw[4] * ty + Rw[5] * tz;
        pw[2] = Rw[6] * tx + Rw[7] * ty + Rw[8] * tz;
    }

    constexpr int PARENT[15] = {0, 1, 2, 3, 4, 3, 6, 7, 8, 9, 3, 11, 12, 13, 14};

#pragma unroll
    for (int e = 0; e < 15; ++e) {
        const int p = PARENT[e];
        const int c = e + 1;

        float R[9];
        rot6d(a[6 * c + 0], a[6 * c + 1], a[6 * c + 2],
              a[6 * c + 3], a[6 * c + 4], a[6 * c + 5], R);

        const float tx = ref[3 * c + 0] - ref[3 * p + 0];
        const float ty = ref[3 * c + 1] - ref[3 * p + 1];
        const float tz = ref[3 * c + 2] - ref[3 * p + 2];

        // local_t = R_c @ t
        const float ltx = R[0] * tx + R[1] * ty + R[2] * tz;
        const float lty = R[3] * tx + R[4] * ty + R[5] * tz;
        const float ltz = R[6] * tx + R[7] * ty + R[8] * tz;

        const float* __restrict__ pR = &Rw[9 * p];

        // Rw[c] = Rw[p] @ R_c
        float* __restrict__ nR = &Rw[9 * c];
#pragma unroll
        for (int i = 0; i < 3; ++i) {
#pragma unroll
            for (int k = 0; k < 3; ++k) {
                nR[3 * i + k] = pR[3 * i + 0] * R[0 + k]
                              + pR[3 * i + 1] * R[3 + k]
                              + pR[3 * i + 2] * R[6 + k];
            }
        }

        // pw[c] = Rw[p] @ local_t + pw[p]
        pw[3 * c + 0] = pR[0] * ltx + pR[1] * lty + pR[2] * ltz + pw[3 * p + 0];
        pw[3 * c + 1] = pR[3] * ltx + pR[4] * lty + pR[5] * ltz + pw[3 * p + 1];
        pw[3 * c + 2] = pR[6] * ltx + pR[7] * lty + pR[8] * ltz + pw[3 * p + 2];
    }

    // Vectorized output: 48 floats = 12 x float4 (base b*192B is 16B-aligned).
    float4* __restrict__ o4 = reinterpret_cast<float4*>(out + (size_t)b * (NJ * 3));
#pragma unroll
    for (int i = 0; i < 12; ++i) {
        o4[i] = make_float4(pw[4 * i + 0], pw[4 * i + 1], pw[4 * i + 2], pw[4 * i + 3]);
    }
}

}  // namespace

extern "C" void kernel_launch(void* const* d_in, const int* in_sizes, int n_in,
                              void* d_out, int out_size) {
    const float* angles = (const float*)d_in[0];
    const float* xyz    = (const float*)d_in[1];
    float* out          = (float*)d_out;

    const int batch = in_sizes[0] / (NJ * 6);  // 262144
    const int threads = 256;
    const int blocks = (batch + threads - 1) / threads;
    skeleton_fk_kernel<<<blocks, threads>>>(angles, xyz, out, batch);
}

// round 2
// speedup vs baseline: 1.5541x; 1.5541x over previous
#include <cuda_runtime.h>
#include <cstdint>

// Skeleton forward kinematics: 6d rotations -> world-space joint positions.
// angles: [B, 16, 6] f32   xyz: [1, 16, 3] f32   out: [B, 16, 3] f32
//
// Round-2 design: smem-transposed tile per block of 128 batch elements.
//  - Coalesced LDG.128 staging into sa[96][129] (transposed: col = batch lane).
//  - Compute reads angles from its private smem column (conflict-free LDS).
//  - pw[c] overwrites consumed angle rows (6c..6c+2) in the private column.
//  - Coalesced float4 output gather after one barrier.

namespace {

constexpr int NJ    = 16;
constexpr int TPB   = 128;
constexpr int AROWS = 96;          // floats per batch element
constexpr int CPAD  = TPB + 1;     // 129: conflict-free column pitch
constexpr int SMEM_FLOATS = AROWS * CPAD + 48;
constexpr size_t SMEM_BYTES = SMEM_FLOATS * sizeof(float);

__device__ __forceinline__ void rot6d(const float a[6], float R[9]) {
    float n1 = rsqrtf(a[0] * a[0] + a[1] * a[1] + a[2] * a[2]);
    float b1x = a[0] * n1, b1y = a[1] * n1, b1z = a[2] * n1;
    float d = b1x * a[3] + b1y * a[4] + b1z * a[5];
    float b2x = a[3] - d * b1x, b2y = a[4] - d * b1y, b2z = a[5] - d * b1z;
    float n2 = rsqrtf(b2x * b2x + b2y * b2y + b2z * b2z);
    b2x *= n2; b2y *= n2; b2z *= n2;
    float b3x = b1y * b2z - b1z * b2y;
    float b3y = b1z * b2x - b1x * b2z;
    float b3z = b1x * b2y - b1y * b2x;
    R[0] = b1x; R[1] = b1y; R[2] = b1z;
    R[3] = b2x; R[4] = b2y; R[5] = b2z;
    R[6] = b3x; R[7] = b3y; R[8] = b3z;
}

__global__ __launch_bounds__(TPB)
void skeleton_fk_tiled(const float4* __restrict__ angles4,
                       const float*  __restrict__ xyz,
                       float4* __restrict__ out4)
{
    extern __shared__ float sm[];
    float* sa   = sm;                  // [96][129] transposed angles -> pw
    float* sref = sm + AROWS * CPAD;   // [48]

    const int t  = threadIdx.x;
    const size_t b0 = (size_t)blockIdx.x * TPB;

    if (t < 48) sref[t] = __ldg(xyz + t);

    // ---- Stage: coalesced LDG.128, transposed STS ----
    const float4* __restrict__ src = angles4 + b0 * 24;  // 24 float4 per batch elem
#pragma unroll
    for (int k = 0; k < 24; ++k) {
        int g = t + k * TPB;           // 0..3071
        float4 v = __ldg(src + g);
        int b  = g / 24;               // local batch 0..127
        int i0 = (g % 24) * 4;         // angle float index 0..92
        sa[(i0 + 0) * CPAD + b] = v.x;
        sa[(i0 + 1) * CPAD + b] = v.y;
        sa[(i0 + 2) * CPAD + b] = v.z;
        sa[(i0 + 3) * CPAD + b] = v.w;
    }
    __syncthreads();

    // ---- Compute FK chain ----
    auto loadA = [&](int c, float* a) {
#pragma unroll
        for (int k = 0; k < 6; ++k) a[k] = sa[(6 * c + k) * CPAD + t];
    };
    auto storePW = [&](int c, const float* p) {
#pragma unroll
        for (int k = 0; k < 3; ++k) sa[(6 * c + k) * CPAD + t] = p[k];
    };

    float Rc[9], pc[3];   // current chain transform
    float Rs[9], ps[3];   // saved at joint 3 (branch point)

    // Root joint 0
    {
        float a[6]; loadA(0, a);
        rot6d(a, Rc);
        float x = sref[0], y = sref[1], z = sref[2];
        pc[0] = Rc[0] * x + Rc[1] * y + Rc[2] * z;
        pc[1] = Rc[3] * x + Rc[4] * y + Rc[5] * z;
        pc[2] = Rc[6] * x + Rc[7] * y + Rc[8] * z;
        storePW(0, pc);
    }

    // One edge: (Rc,pc) <- parent (Rc,pc) composed with child c rotation.
    auto step = [&](int p, int c) {
        float a[6]; loadA(c, a);
        float R[9]; rot6d(a, R);

        float tx = sref[3 * c + 0] - sref[3 * p + 0];
        float ty = sref[3 * c + 1] - sref[3 * p + 1];
        float tz = sref[3 * c + 2] - sref[3 * p + 2];

        float ltx = R[0] * tx + R[1] * ty + R[2] * tz;
        float lty = R[3] * tx + R[4] * ty + R[5] * tz;
        float ltz = R[6] * tx + R[7] * ty + R[8] * tz;

        float Rn[9];
#pragma unroll
        for (int i = 0; i < 3; ++i) {
#pragma unroll
            for (int k = 0; k < 3; ++k) {
                Rn[3 * i + k] = Rc[3 * i + 0] * R[0 + k]
                              + Rc[3 * i + 1] * R[3 + k]
                              + Rc[3 * i + 2] * R[6 + k];
            }
        }
        float pn[3];
        pn[0] = Rc[0] * ltx + Rc[1] * lty + Rc[2] * ltz + pc[0];
        pn[1] = Rc[3] * ltx + Rc[4] * lty + Rc[5] * ltz + pc[1];
        pn[2] = Rc[6] * ltx + Rc[7] * lty + Rc[8] * ltz + pc[2];

#pragma unroll
        for (int i = 0; i < 9; ++i) Rc[i] = Rn[i];
#pragma unroll
        for (int i = 0; i < 3; ++i) pc[i] = pn[i];
        storePW(c, pc);
    };

    // Chain 0-1-2-3
    step(0, 1); step(1, 2); step(2, 3);
    // Save branch point
#pragma unroll
    for (int i = 0; i < 9; ++i) Rs[i] = Rc[i];
#pragma unroll
    for (int i = 0; i < 3; ++i) ps[i] = pc[i];

    // Branch A: 3-4-5
    step(3, 4); step(4, 5);

    // Branch B: 3-6-7-8-9-10
#pragma unroll
    for (int i = 0; i < 9; ++i) Rc[i] = Rs[i];
#pragma unroll
    for (int i = 0; i < 3; ++i) pc[i] = ps[i];
    step(3, 6); step(6, 7); step(7, 8); step(8, 9); step(9, 10);

    // Branch C: 3-11-12-13-14-15
#pragma unroll
    for (int i = 0; i < 9; ++i) Rc[i] = Rs[i];
#pragma unroll
    for (int i = 0; i < 3; ++i) pc[i] = ps[i];
    step(3, 11); step(11, 12); step(12, 13); step(13, 14); step(14, 15);

    __syncthreads();

    // ---- Coalesced float4 output gather ----
    float4* __restrict__ dst = out4 + b0 * 12;   // 12 float4 per batch elem
#pragma unroll
    for (int k = 0; k < 12; ++k) {
        int g  = t + k * TPB;        // 0..1535
        int f0 = g * 4;              // first output float index in tile
        int b  = f0 / 48;            // same b for all 4 components (f0 % 4 == 0)
        int r0 = f0 % 48;
        float v[4];
#pragma unroll
        for (int m = 0; m < 4; ++m) {
            int rem  = r0 + m;
            int j    = rem / 3;
            int comp = rem - 3 * j;
            v[m] = sa[(6 * j + comp) * CPAD + b];
        }
        dst[g] = make_float4(v[0], v[1], v[2], v[3]);
    }
}

// Fallback for a partial tail (not expected for BATCH=262144, kept for safety).
__global__ void skeleton_fk_tail(const float* __restrict__ angles,
                                 const float* __restrict__ xyz,
                                 float* __restrict__ out,
                                 int start, int batch)
{
    int b = start + blockIdx.x * blockDim.x + threadIdx.x;
    if (b >= batch) return;
    const float* ab = angles + (size_t)b * (NJ * 6);
    float ref[NJ * 3];
#pragma unroll
    for (int i = 0; i < NJ * 3; ++i) ref[i] = __ldg(xyz + i);

    float Rw[NJ * 9], pw[NJ * 3];
    {
        float a[6];
#pragma unroll
        for (int k = 0; k < 6; ++k) a[k] = ab[k];
        rot6d(a, &Rw[0]);
        float x = ref[0], y = ref[1], z = ref[2];
        pw[0] = Rw[0] * x + Rw[1] * y + Rw[2] * z;
        pw[1] = Rw[3] * x + Rw[4] * y + Rw[5] * z;
        pw[2] = Rw[6] * x + Rw[7] * y + Rw[8] * z;
    }
    constexpr int PARENT[15] = {0, 1, 2, 3, 4, 3, 6, 7, 8, 9, 3, 11, 12, 13, 14};
#pragma unroll
    for (int e = 0; e < 15; ++e) {
        const int p = PARENT[e], c = e + 1;
        float a[6];
#pragma unroll
        for (int k = 0; k < 6; ++k) a[k] = ab[6 * c + k];
        float R[9]; rot6d(a, R);
        float tx = ref[3 * c + 0] - ref[3 * p + 0];
        float ty = ref[3 * c + 1] - ref[3 * p + 1];
        float tz = ref[3 * c + 2] - ref[3 * p + 2];
        float ltx = R[0] * tx + R[1] * ty + R[2] * tz;
        float lty = R[3] * tx + R[4] * ty + R[5] * tz;
        float ltz = R[6] * tx + R[7] * ty + R[8] * tz;
        const float* pR = &Rw[9 * p];
        float* nR = &Rw[9 * c];
#pragma unroll
        for (int i = 0; i < 3; ++i)
#pragma unroll
            for (int k = 0; k < 3; ++k)
                nR[3 * i + k] = pR[3 * i + 0] * R[k] + pR[3 * i + 1] * R[3 + k] + pR[3 * i + 2] * R[6 + k];
        pw[3 * c + 0] = pR[0] * ltx + pR[1] * lty + pR[2] * ltz + pw[3 * p + 0];
        pw[3 * c + 1] = pR[3] * ltx + pR[4] * lty + pR[5] * ltz + pw[3 * p + 1];
        pw[3 * c + 2] = pR[6] * ltx + pR[7] * lty + pR[8] * ltz + pw[3 * p + 2];
    }
    float* o = out + (size_t)b * (NJ * 3);
#pragma unroll
    for (int i = 0; i < NJ * 3; ++i) o[i] = pw[i];
}

}  // namespace

extern "C" void kernel_launch(void* const* d_in, const int* in_sizes, int n_in,
                              void* d_out, int out_size) {
    const float* angles = (const float*)d_in[0];
    const float* xyz    = (const float*)d_in[1];
    float* out          = (float*)d_out;

    const int batch = in_sizes[0] / (NJ * 6);
    const int full  = batch / TPB;

    cudaFuncSetAttribute(skeleton_fk_tiled,
                         cudaFuncAttributeMaxDynamicSharedMemorySize,
                         (int)SMEM_BYTES);

    if (full > 0) {
        skeleton_fk_tiled<<<full, TPB, SMEM_BYTES>>>(
            (const float4*)angles, xyz, (float4*)out);
    }
    const int rem = batch - full * TPB;
    if (rem > 0) {
        skeleton_fk_tail<<<(rem + 127) / 128, 128>>>(angles, xyz, out,
                                                     full * TPB, batch);
    }
}

// round 3
// speedup vs baseline: 1.9307x; 1.2423x over previous
#include <cuda_runtime.h>
#include <cstdint>

// Skeleton forward kinematics: 6d rotations -> world-space joint positions.
// angles: [B, 16, 6] f32   xyz: [1, 16, 3] f32   out: [B, 16, 3] f32
//
// Round-3: all-float4 shared-memory pipeline, pitch-129 conflict-free layout.
//   sa4[r * 129 + b] : r = 0..23 (float4 row within element), b = 0..127 (lane).
//   stage (24 STS.128) -> compute (24 LDS.128, pw flushed as 12 STS.128 into
//   consumed rows) -> gather (12 LDS.128 + 12 coalesced STG.128).

namespace {

constexpr int NJ   = 16;
constexpr int TPB  = 128;
constexpr int PIT  = 129;                       // float4 pitch (odd -> no conflicts)
constexpr size_t SMEM_BYTES = 24 * PIT * sizeof(float4) + 48 * sizeof(float);

__device__ __forceinline__ void rot6d(const float* __restrict__ a, float R[9]) {
    float n1 = rsqrtf(a[0] * a[0] + a[1] * a[1] + a[2] * a[2]);
    float b1x = a[0] * n1, b1y = a[1] * n1, b1z = a[2] * n1;
    float d = b1x * a[3] + b1y * a[4] + b1z * a[5];
    float b2x = a[3] - d * b1x, b2y = a[4] - d * b1y, b2z = a[5] - d * b1z;
    float n2 = rsqrtf(b2x * b2x + b2y * b2y + b2z * b2z);
    b2x *= n2; b2y *= n2; b2z *= n2;
    R[0] = b1x; R[1] = b1y; R[2] = b1z;
    R[3] = b2x; R[4] = b2y; R[5] = b2z;
    R[6] = b1y * b2z - b1z * b2y;
    R[7] = b1z * b2x - b1x * b2z;
    R[8] = b1x * b2y - b1y * b2x;
}

__global__ __launch_bounds__(TPB)
void skeleton_fk_v3(const float4* __restrict__ angles4,
                    const float*  __restrict__ xyz,
                    float4* __restrict__ out4)
{
    extern __shared__ float4 sa4[];                   // [24 * PIT]
    float* sref = reinterpret_cast<float*>(sa4 + 24 * PIT);   // [48]

    const int t = threadIdx.x;
    const size_t tile = (size_t)blockIdx.x * TPB;

    // ---- Stage: coalesced LDG.128 -> conflict-free STS.128 ----
    const float4* __restrict__ src = angles4 + tile * 24;
#pragma unroll
    for (int k = 0; k < 24; ++k) {
        int g = t + k * TPB;                 // 0..3071
        float4 v = __ldg(src + g);
        int b = g / 24;
        int r = g - b * 24;
        sa4[r * PIT + b] = v;
    }
    if (t < 48) sref[t] = __ldg(xyz + t);
    __syncthreads();

    // ---- Compute ----
    float a2[12];                            // angles for current joint pair
    float pw[48];                            // world positions (flushed early)
    float Rc[9], pc[3], Rs[9], ps[3];

    auto loadPair = [&](int j) {             // joints 2j, 2j+1 -> a2[0..11]
        float4 q0 = sa4[(3 * j + 0) * PIT + t];
        float4 q1 = sa4[(3 * j + 1) * PIT + t];
        float4 q2 = sa4[(3 * j + 2) * PIT + t];
        a2[0] = q0.x; a2[1] = q0.y; a2[2]  = q0.z; a2[3]  = q0.w;
        a2[4] = q1.x; a2[5] = q1.y; a2[6]  = q1.z; a2[7]  = q1.w;
        a2[8] = q2.x; a2[9] = q2.y; a2[10] = q2.z; a2[11] = q2.w;
    };
    auto flushRow = [&](int r) {             // pw float4 r -> own column
        sa4[r * PIT + t] = make_float4(pw[4 * r + 0], pw[4 * r + 1],
                                       pw[4 * r + 2], pw[4 * r + 3]);
    };
    auto step = [&](int p, int c, int ao) {  // compose edge p->c
        float R[9];
        rot6d(&a2[ao], R);
        float tx = sref[3 * c + 0] - sref[3 * p + 0];
        float ty = sref[3 * c + 1] - sref[3 * p + 1];
        float tz = sref[3 * c + 2] - sref[3 * p + 2];
        float ltx = R[0] * tx + R[1] * ty + R[2] * tz;
        float lty = R[3] * tx + R[4] * ty + R[5] * tz;
        float ltz = R[6] * tx + R[7] * ty + R[8] * tz;
        float Rn[9];
#pragma unroll
        for (int i = 0; i < 3; ++i)
#pragma unroll
            for (int k = 0; k < 3; ++k)
                Rn[3 * i + k] = Rc[3 * i + 0] * R[0 + k]
                              + Rc[3 * i + 1] * R[3 + k]
                              + Rc[3 * i + 2] * R[6 + k];
        pw[3 * c + 0] = Rc[0] * ltx + Rc[1] * lty + Rc[2] * ltz + pw[3 * p + 0];
        pw[3 * c + 1] = Rc[3] * ltx + Rc[4] * lty + Rc[5] * ltz + pw[3 * p + 1];
        pw[3 * c + 2] = Rc[6] * ltx + Rc[7] * lty + Rc[8] * ltz + pw[3 * p + 2];
#pragma unroll
        for (int i = 0; i < 9; ++i) Rc[i] = Rn[i];
    };
    auto save = [&]() {
#pragma unroll
        for (int i = 0; i < 9; ++i) Rs[i] = Rc[i];
        ps[0] = pw[9]; ps[1] = pw[10]; ps[2] = pw[11];
    };
    auto restore = [&]() {
#pragma unroll
        for (int i = 0; i < 9; ++i) Rc[i] = Rs[i];
        (void)ps;  // pw[9..11] untouched; parent reads come from pw directly
    };

    // Root joint 0
    loadPair(0);
    rot6d(&a2[0], Rc);
    {
        float x = sref[0], y = sref[1], z = sref[2];
        pw[0] = Rc[0] * x + Rc[1] * y + Rc[2] * z;
        pw[1] = Rc[3] * x + Rc[4] * y + Rc[5] * z;
        pw[2] = Rc[6] * x + Rc[7] * y + Rc[8] * z;
    }
    (void)pc;

    // Chain 0-1-2-3        (flush r after joint c when 4r+3 <= 3c+2)
    step(0, 1, 6);  flushRow(0);
    loadPair(1);
    step(1, 2, 0);  flushRow(1);
    step(2, 3, 6);  flushRow(2);
    save();

    // Branch A: 3-4-5
    loadPair(2);
    step(3, 4, 0);
    step(4, 5, 6);  flushRow(3);

    // Branch B: 3-6-7-8-9-10
    restore();
    loadPair(3);
    step(3, 6, 0);  flushRow(4);
    step(6, 7, 6);  flushRow(5);
    loadPair(4);
    step(7, 8, 0);
    step(8, 9, 6);  flushRow(6);
    loadPair(5);
    step(9, 10, 0); flushRow(7);

    // Branch C: 3-11-12-13-14-15
    restore();
    step(3, 11, 6);  flushRow(8);
    loadPair(6);
    step(11, 12, 0);
    step(12, 13, 6); flushRow(9);
    loadPair(7);
    step(13, 14, 0); flushRow(10);
    step(14, 15, 6); flushRow(11);

    __syncthreads();

    // ---- Gather: conflict-free LDS.128 -> coalesced STG.128 ----
    float4* __restrict__ dst = out4 + tile * 12;
#pragma unroll
    for (int k = 0; k < 12; ++k) {
        int g = t + k * TPB;                 // 0..1535
        int b = g / 12;
        int r = g - b * 12;
        dst[g] = sa4[r * PIT + b];
    }
}

// Tail fallback (batch not a multiple of TPB; unused for BATCH=262144).
__global__ void skeleton_fk_tail(const float* __restrict__ angles,
                                 const float* __restrict__ xyz,
                                 float* __restrict__ out,
                                 int start, int batch)
{
    int b = start + blockIdx.x * blockDim.x + threadIdx.x;
    if (b >= batch) return;
    const float* ab = angles + (size_t)b * (NJ * 6);
    float ref[NJ * 3];
#pragma unroll
    for (int i = 0; i < NJ * 3; ++i) ref[i] = __ldg(xyz + i);

    float Rw[NJ * 9], pw[NJ * 3];
    {
        float a[6];
#pragma unroll
        for (int k = 0; k < 6; ++k) a[k] = ab[k];
        rot6d(a, &Rw[0]);
        float x = ref[0], y = ref[1], z = ref[2];
        pw[0] = Rw[0] * x + Rw[1] * y + Rw[2] * z;
        pw[1] = Rw[3] * x + Rw[4] * y + Rw[5] * z;
        pw[2] = Rw[6] * x + Rw[7] * y + Rw[8] * z;
    }
    constexpr int PARENT[15] = {0, 1, 2, 3, 4, 3, 6, 7, 8, 9, 3, 11, 12, 13, 14};
#pragma unroll
    for (int e = 0; e < 15; ++e) {
        const int p = PARENT[e], c = e + 1;
        float a[6];
#pragma unroll
        for (int k = 0; k < 6; ++k) a[k] = ab[6 * c + k];
        float R[9]; rot6d(a, R);
        float tx = ref[3 * c + 0] - ref[3 * p + 0];
        float ty = ref[3 * c + 1] - ref[3 * p + 1];
        float tz = ref[3 * c + 2] - ref[3 * p + 2];
        float ltx = R[0] * tx + R[1] * ty + R[2] * tz;
        float lty = R[3] * tx + R[4] * ty + R[5] * tz;
        float ltz = R[6] * tx + R[7] * ty + R[8] * tz;
        const float* pR = &Rw[9 * p];
        float* nR = &Rw[9 * c];
#pragma unroll
        for (int i = 0; i < 3; ++i)
#pragma unroll
            for (int k = 0; k < 3; ++k)
                nR[3 * i + k] = pR[3 * i + 0] * R[k] + pR[3 * i + 1] * R[3 + k]
                              + pR[3 * i + 2] * R[6 + k];
        pw[3 * c + 0] = pR[0] * ltx + pR[1] * lty + pR[2] * ltz + pw[3 * p + 0];
        pw[3 * c + 1] = pR[3] * ltx + pR[4] * lty + pR[5] * ltz + pw[3 * p + 1];
        pw[3 * c + 2] = pR[6] * ltx + pR[7] * lty + pR[8] * ltz + pw[3 * p + 2];
    }
    float* o = out + (size_t)b * (NJ * 3);
#pragma unroll
    for (int i = 0; i < NJ * 3; ++i) o[i] = pw[i];
}

}  // namespace

extern "C" void kernel_launch(void* const* d_in, const int* in_sizes, int n_in,
                              void* d_out, int out_size) {
    const float* angles = (const float*)d_in[0];
    const float* xyz    = (const float*)d_in[1];
    float* out          = (float*)d_out;

    const int batch = in_sizes[0] / (NJ * 6);
    const int full  = batch / TPB;

    cudaFuncSetAttribute(skeleton_fk_v3,
                         cudaFuncAttributeMaxDynamicSharedMemorySize,
                         (int)SMEM_BYTES);

    if (full > 0) {
        skeleton_fk_v3<<<full, TPB, SMEM_BYTES>>>(
            (const float4*)angles, xyz, (float4*)out);
    }
    const int rem = batch - full * TPB;
    if (rem > 0) {
        skeleton_fk_tail<<<(rem + 127) / 128, 128>>>(angles, xyz, out,
                                                     full * TPB, batch);
    }
}